// round 5
// baseline (speedup 1.0000x reference)
#include <cuda_runtime.h>
#include <cuda_fp16.h>
#include <cstdint>
#include <cstddef>

#define NTOK 8192
#define IN_DIM 1024
#define HID_DIM 4096
#define OUT_DIM 1024
#define NE 8

// Scratch
__device__ __half g_xh[(size_t)NTOK * IN_DIM];            // x in fp16
__device__ __half g_w1t[(size_t)NE * HID_DIM * IN_DIM];   // W1^T [E][HID][IN] fp16
__device__ __half g_w2t[(size_t)NE * OUT_DIM * HID_DIM];  // W2^T [E][OUT][HID] fp16
__device__ __half g_hh[(size_t)NE * NTOK * HID_DIM];      // h fp16 (GEMM1 out, LN in-place)
__device__ __half g_yh[(size_t)NE * NTOK * OUT_DIM];      // y fp16 (GEMM2 out)

// ---------------- helpers ----------------
__device__ __forceinline__ float geluf(float x) {
    return 0.5f * x * (1.0f + erff(x * 0.70710678118654752f));
}
__device__ __forceinline__ uint32_t smem_u32(const void* p) {
    uint32_t a;
    asm("{ .reg .u64 t; cvta.to.shared.u64 t, %1; cvt.u32.u64 %0, t; }" : "=r"(a) : "l"(p));
    return a;
}
__device__ __forceinline__ void cpa16(uint32_t dst, const void* src) {
    asm volatile("cp.async.cg.shared.global [%0], [%1], 16;" :: "r"(dst), "l"(src));
}

#define LDM4(r, addr)                                                            \
    asm volatile("ldmatrix.sync.aligned.m8n8.x4.shared.b16 {%0,%1,%2,%3}, [%4];" \
                 : "=r"((r)[0]), "=r"((r)[1]), "=r"((r)[2]), "=r"((r)[3])        \
                 : "r"(addr))

#define MMA16816(c, a, b0, b1)                                                   \
    asm volatile("mma.sync.aligned.m16n8k16.row.col.f32.f16.f16.f32 "            \
                 "{%0,%1,%2,%3}, {%4,%5,%6,%7}, {%8,%9}, {%0,%1,%2,%3};"         \
                 : "+f"((c)[0]), "+f"((c)[1]), "+f"((c)[2]), "+f"((c)[3])        \
                 : "r"((a)[0]), "r"((a)[1]), "r"((a)[2]), "r"((a)[3]),           \
                   "r"(b0), "r"(b1))

// ---------------- fp16 mma.sync GEMM: C[e] = A @ Bt[e]^T + bias[e], fp16 out ----------------
// CTA 128x128, 256 threads (8 warps, 4M x 2N), warp tile 32x64. 2 CTAs/SM.
#define BM 128
#define BN 128
#define BKH 32                  // halves of K per stage
#define NSTAGE 4
#define ROWB 80                 // smem row stride bytes (64 data + 16 pad)
#define A_BYTES (BM * ROWB)     // 10240
#define B_BYTES (BN * ROWB)     // 10240
#define STAGE_BYTES (A_BYTES + B_BYTES)
#define SMEM_GEMM (NSTAGE * STAGE_BYTES)   // 81920

template <bool FIRST>
__global__ void __launch_bounds__(256, 2) gemm_h(
    const __half* __restrict__ A, const __half* __restrict__ Bt,
    const float* __restrict__ bias, __half* __restrict__ C) {
    constexpr int K = FIRST ? IN_DIM : HID_DIM;
    constexpr int N = FIRST ? HID_DIM : OUT_DIM;
    constexpr int NKT = K / BKH;

    extern __shared__ char smem[];
    const uint32_t sb = smem_u32(smem);

    const int tid = threadIdx.x, lane = tid & 31, wid = tid >> 5;
    const int e = blockIdx.z, m0 = blockIdx.x * BM, n0 = blockIdx.y * BN;

    const __half* Ae = A + (FIRST ? (size_t)0 : (size_t)e * NTOK * K) + (size_t)m0 * K;
    const __half* Be = Bt + (size_t)e * (size_t)N * K + (size_t)n0 * K;
    __half* Ce = C + (size_t)e * NTOK * N;

    // loaders (256 threads): A/B each 128 rows x 4 x 16B chunks = 512 chunks, 2 per thread
    const int r0c = tid >> 1, c0c = (tid & 1) * 2;       // chunk pair layout: row, col(0/2)
    const __half* aG0 = Ae + (size_t)r0c * K + c0c * 8;
    const __half* bG0 = Be + (size_t)r0c * K + c0c * 8;
    const uint32_t s0 = (uint32_t)(r0c * ROWB + c0c * 16);

#define LOADST(c, s) do {                                                   \
        uint32_t _b = sb + (uint32_t)(s) * STAGE_BYTES;                     \
        const __half* _ag = aG0 + (size_t)(c) * BKH;                        \
        const __half* _bg = bG0 + (size_t)(c) * BKH;                        \
        cpa16(_b + s0, _ag); cpa16(_b + s0 + 16, _ag + 8);                  \
        uint32_t _bb = _b + A_BYTES + s0;                                   \
        cpa16(_bb, _bg); cpa16(_bb + 16, _bg + 8);                          \
    } while (0)

    // warp tile 32(M) x 64(N): warps 4(M) x 2(N)
    const int wm = (wid >> 1) * 32, wn = (wid & 1) * 64;
    const uint32_t lrow = (uint32_t)(lane & 15);
    const uint32_t lhalf = (uint32_t)((lane >> 4) * 16);
    const uint32_t aLd = (uint32_t)((wm + lrow) * ROWB) + lhalf;
    const uint32_t bLd = A_BYTES + (uint32_t)((wn + lrow) * ROWB) + lhalf;

    float acc[2][8][4];
#pragma unroll
    for (int i = 0; i < 2; i++)
#pragma unroll
        for (int j = 0; j < 8; j++)
#pragma unroll
            for (int r = 0; r < 4; r++) acc[i][j][r] = 0.0f;

    // prologue: 3 stages in flight
#pragma unroll
    for (int c = 0; c < NSTAGE - 1; c++) {
        LOADST(c, c);
        asm volatile("cp.async.commit_group;" ::: "memory");
    }

    for (int kt = 0; kt < NKT; kt++) {
        asm volatile("cp.async.wait_group 2;" ::: "memory");
        __syncthreads();
        if (kt + NSTAGE - 1 < NKT) LOADST(kt + NSTAGE - 1, (kt + NSTAGE - 1) & (NSTAGE - 1));
        asm volatile("cp.async.commit_group;" ::: "memory");

        const uint32_t base = sb + (uint32_t)(kt & (NSTAGE - 1)) * STAGE_BYTES;
#pragma unroll
        for (int ks = 0; ks < 2; ks++) {
            const uint32_t koff = (uint32_t)(ks * 32);
            uint32_t af[2][4], br[4][4];
#pragma unroll
            for (int i = 0; i < 2; i++) LDM4(af[i], base + aLd + i * (16 * ROWB) + koff);
#pragma unroll
            for (int t = 0; t < 4; t++) LDM4(br[t], base + bLd + t * (16 * ROWB) + koff);
#pragma unroll
            for (int i = 0; i < 2; i++)
#pragma unroll
                for (int j = 0; j < 8; j++) {
                    const int t = j >> 1;
                    const uint32_t b0 = (j & 1) ? br[t][1] : br[t][0];
                    const uint32_t b1 = (j & 1) ? br[t][3] : br[t][2];
                    MMA16816(acc[i][j], af[i], b0, b1);
                }
        }
    }

    // epilogue: bias add, fp16 store
    const int g = lane >> 2, tg = lane & 3;
#pragma unroll
    for (int i = 0; i < 2; i++) {
        const int row = m0 + wm + i * 16 + g;
#pragma unroll
        for (int j = 0; j < 8; j++) {
            const int col = n0 + wn + j * 8 + tg * 2;
            const float bv0 = bias[(size_t)e * N + col];
            const float bv1 = bias[(size_t)e * N + col + 1];
            *(__half2*)(Ce + (size_t)row * N + col) =
                __floats2half2_rn(acc[i][j][0] + bv0, acc[i][j][1] + bv1);
            *(__half2*)(Ce + (size_t)(row + 8) * N + col) =
                __floats2half2_rn(acc[i][j][2] + bv0, acc[i][j][3] + bv1);
        }
    }
#undef LOADST
}

// ---------------- weight transpose + fp16 convert: [K,N] -> [N,K] ----------------
template <bool W1SEL>
__global__ void transpose_h(const float* __restrict__ in, int K, int N) {
    __shared__ float t[32][33];
    __half* out = W1SEL ? g_w1t : g_w2t;
    const int e = blockIdx.z;
    const float* ip = in + (size_t)e * K * N;
    __half* op = out + (size_t)e * K * N;
    const int n0 = blockIdx.x * 32, k0 = blockIdx.y * 32;
#pragma unroll
    for (int r = threadIdx.y; r < 32; r += 8)
        t[r][threadIdx.x] = ip[(size_t)(k0 + r) * N + n0 + threadIdx.x];
    __syncthreads();
#pragma unroll
    for (int r = threadIdx.y; r < 32; r += 8)
        op[(size_t)(n0 + r) * K + k0 + threadIdx.x] = __float2half_rn(t[threadIdx.x][r]);
}

// x -> g_xh fp16
__global__ void copy_h(const float* __restrict__ in) {
    const size_t i = ((size_t)blockIdx.x * 256 + threadIdx.x) * 4;
    float4 v = *(const float4*)(in + i);
    __half2* o = (__half2*)(g_xh + i);
    o[0] = __floats2half2_rn(v.x, v.y);
    o[1] = __floats2half2_rn(v.z, v.w);
}

// ---------------- LayerNorm + GELU in place on g_hh (fp16 rows of HID_DIM) ----------------
__global__ void __launch_bounds__(256) ln_gelu_kernel(
    const float* __restrict__ gamma, const float* __restrict__ beta) {
    __shared__ float red[16];
    const size_t row = blockIdx.x;
    const int e = blockIdx.x >> 13;
    __half* p = g_hh + row * (size_t)HID_DIM;
    const float* gm = gamma + (size_t)e * HID_DIM;
    const float* bt = beta + (size_t)e * HID_DIM;
    const int tid = threadIdx.x;

    float vals[16];
    float s = 0.f, s2 = 0.f;
#pragma unroll
    for (int r = 0; r < 4; r++) {
        const int i = tid * 4 + r * 1024;
        __half2 h0 = *(const __half2*)(p + i);
        __half2 h1 = *(const __half2*)(p + i + 2);
        float2 f0 = __half22float2(h0), f1 = __half22float2(h1);
        vals[r * 4 + 0] = f0.x; vals[r * 4 + 1] = f0.y;
        vals[r * 4 + 2] = f1.x; vals[r * 4 + 3] = f1.y;
        s  += f0.x + f0.y + f1.x + f1.y;
        s2 += f0.x * f0.x + f0.y * f0.y + f1.x * f1.x + f1.y * f1.y;
    }
#pragma unroll
    for (int o = 16; o > 0; o >>= 1) {
        s  += __shfl_xor_sync(0xffffffffu, s, o);
        s2 += __shfl_xor_sync(0xffffffffu, s2, o);
    }
    const int wi = tid >> 5, ln = tid & 31;
    if (ln == 0) { red[wi] = s; red[8 + wi] = s2; }
    __syncthreads();
    if (tid == 0) {
        float ts = 0.f, t2 = 0.f;
        for (int k = 0; k < 8; k++) { ts += red[k]; t2 += red[8 + k]; }
        red[0] = ts; red[8] = t2;
    }
    __syncthreads();
    const float invL = 1.0f / (float)HID_DIM;
    const float mean = red[0] * invL;
    const float inv = rsqrtf(red[8] * invL - mean * mean + 1e-5f);
#pragma unroll
    for (int r = 0; r < 4; r++) {
        const int i = tid * 4 + r * 1024;
        float4 gv = *(const float4*)(gm + i);
        float4 bv = *(const float4*)(bt + i);
        float r0 = geluf((vals[r * 4 + 0] - mean) * inv * gv.x + bv.x);
        float r1 = geluf((vals[r * 4 + 1] - mean) * inv * gv.y + bv.y);
        float r2 = geluf((vals[r * 4 + 2] - mean) * inv * gv.z + bv.z);
        float r3 = geluf((vals[r * 4 + 3] - mean) * inv * gv.w + bv.w);
        *(__half2*)(p + i)     = __floats2half2_rn(r0, r1);
        *(__half2*)(p + i + 2) = __floats2half2_rn(r2, r3);
    }
}

// -------- Final: LN(OUT) + GELU per (e,b), weighted sum over e --------
__global__ void __launch_bounds__(256) final_kernel(
    const float* __restrict__ weights, const float* __restrict__ gamma,
    const float* __restrict__ beta, float* __restrict__ out) {
    __shared__ float red[16];
    const int b = blockIdx.x;
    const int tid = threadIdx.x;
    const int wi = tid >> 5, ln = tid & 31;

    float accv[4] = {0.f, 0.f, 0.f, 0.f};
#pragma unroll 1
    for (int e = 0; e < NE; e++) {
        const __half* p = g_yh + ((size_t)e * NTOK + b) * OUT_DIM;
        float vals[4];
        float s = 0.f, s2 = 0.f;
#pragma unroll
        for (int r = 0; r < 4; r++) {
            float v = __half2float(p[tid + r * 256]);
            vals[r] = v;
            s += v; s2 += v * v;
        }
#pragma unroll
        for (int o = 16; o > 0; o >>= 1) {
            s  += __shfl_xor_sync(0xffffffffu, s, o);
            s2 += __shfl_xor_sync(0xffffffffu, s2, o);
        }
        if (ln == 0) { red[wi] = s; red[8 + wi] = s2; }
        __syncthreads();
        if (tid == 0) {
            float ts = 0.f, t2 = 0.f;
            for (int k = 0; k < 8; k++) { ts += red[k]; t2 += red[8 + k]; }
            red[0] = ts; red[8] = t2;
        }
        __syncthreads();
        const float invL = 1.0f / (float)OUT_DIM;
        const float mean = red[0] * invL;
        const float inv = rsqrtf(red[8] * invL - mean * mean + 1e-5f);
        const float w = weights[(size_t)b * NE + e];
#pragma unroll
        for (int r = 0; r < 4; r++) {
            const int i = tid + r * 256;
            const float v = (vals[r] - mean) * inv * gamma[(size_t)e * OUT_DIM + i]
                          + beta[(size_t)e * OUT_DIM + i];
            accv[r] += w * geluf(v);
        }
        __syncthreads();
    }
#pragma unroll
    for (int r = 0; r < 4; r++)
        out[(size_t)b * OUT_DIM + tid + r * 256] = accv[r];
}

// ---------------- launch ----------------
extern "C" void kernel_launch(void* const* d_in, const int* in_sizes, int n_in,
                              void* d_out, int out_size) {
    const float* x   = (const float*)d_in[0];
    const float* wts = (const float*)d_in[1];
    const float* W1  = (const float*)d_in[2];
    const float* b1  = (const float*)d_in[3];
    const float* g1  = (const float*)d_in[4];
    const float* be1 = (const float*)d_in[5];
    const float* W2  = (const float*)d_in[6];
    const float* b2  = (const float*)d_in[7];
    const float* g2  = (const float*)d_in[8];
    const float* be2 = (const float*)d_in[9];
    float* out = (float*)d_out;

    cudaFuncSetAttribute(gemm_h<true>,  cudaFuncAttributeMaxDynamicSharedMemorySize, SMEM_GEMM);
    cudaFuncSetAttribute(gemm_h<false>, cudaFuncAttributeMaxDynamicSharedMemorySize, SMEM_GEMM);

    __half* w1t; cudaGetSymbolAddress((void**)&w1t, g_w1t);
    __half* w2t; cudaGetSymbolAddress((void**)&w2t, g_w2t);
    __half* xh;  cudaGetSymbolAddress((void**)&xh,  g_xh);
    __half* hh;  cudaGetSymbolAddress((void**)&hh,  g_hh);
    __half* yh;  cudaGetSymbolAddress((void**)&yh,  g_yh);

    // prep: transpose+convert weights, convert x
    transpose_h<true ><<<dim3(HID_DIM / 32, IN_DIM / 32, NE), dim3(32, 8)>>>(W1, IN_DIM, HID_DIM);
    transpose_h<false><<<dim3(OUT_DIM / 32, HID_DIM / 32, NE), dim3(32, 8)>>>(W2, HID_DIM, OUT_DIM);
    copy_h<<<(NTOK * IN_DIM) / 1024, 256>>>(x);

    // GEMM1: g_hh = x @ W1 + b1  (fp16)
    gemm_h<true><<<dim3(NTOK / BM, HID_DIM / BN, NE), 256, SMEM_GEMM>>>(xh, w1t, b1, hh);
    // LN + GELU in place on g_hh
    ln_gelu_kernel<<<NE * NTOK, 256>>>(g1, be1);
    // GEMM2: g_yh = hh @ W2 + b2 (fp16)
    gemm_h<false><<<dim3(NTOK / BM, OUT_DIM / BN, NE), 256, SMEM_GEMM>>>(hh, w2t, b2, yh);
    // final LN + GELU + weighted combine
    final_kernel<<<NTOK, 256>>>(wts, g2, be2, out);
}

// round 6
// speedup vs baseline: 1.0003x; 1.0003x over previous
#include <cuda_runtime.h>
#include <cuda_fp16.h>
#include <cstdint>
#include <cstddef>

#define NTOK 8192
#define IN_DIM 1024
#define HID_DIM 4096
#define OUT_DIM 1024
#define NE 8

// Scratch
__device__ __half g_xh[(size_t)NTOK * IN_DIM];            // x in fp16
__device__ __half g_w1t[(size_t)NE * HID_DIM * IN_DIM];   // W1^T [E][HID][IN] fp16
__device__ __half g_w2t[(size_t)NE * OUT_DIM * HID_DIM];  // W2^T [E][OUT][HID] fp16
__device__ __half g_hh[(size_t)NE * NTOK * HID_DIM];      // h fp16 (GEMM1 out, LN in-place)
__device__ __half g_yh[(size_t)NE * NTOK * OUT_DIM];      // y fp16 (GEMM2 out)

// ---------------- helpers ----------------
__device__ __forceinline__ float geluf(float x) {
    return 0.5f * x * (1.0f + erff(x * 0.70710678118654752f));
}
__device__ __forceinline__ uint32_t smem_u32(const void* p) {
    uint32_t a;
    asm("{ .reg .u64 t; cvta.to.shared.u64 t, %1; cvt.u32.u64 %0, t; }" : "=r"(a) : "l"(p));
    return a;
}
__device__ __forceinline__ void cpa16(uint32_t dst, const void* src) {
    asm volatile("cp.async.cg.shared.global [%0], [%1], 16;" :: "r"(dst), "l"(src));
}

#define LDM4(r, addr)                                                            \
    asm volatile("ldmatrix.sync.aligned.m8n8.x4.shared.b16 {%0,%1,%2,%3}, [%4];" \
                 : "=r"((r)[0]), "=r"((r)[1]), "=r"((r)[2]), "=r"((r)[3])        \
                 : "r"(addr))

#define MMA16816(c, a, b0, b1)                                                   \
    asm volatile("mma.sync.aligned.m16n8k16.row.col.f32.f16.f16.f32 "            \
                 "{%0,%1,%2,%3}, {%4,%5,%6,%7}, {%8,%9}, {%0,%1,%2,%3};"         \
                 : "+f"((c)[0]), "+f"((c)[1]), "+f"((c)[2]), "+f"((c)[3])        \
                 : "r"((a)[0]), "r"((a)[1]), "r"((a)[2]), "r"((a)[3]),           \
                   "r"(b0), "r"(b1))

// ---------------- fp16 mma.sync GEMM: C[e] = A @ Bt[e]^T + bias[e], fp16 out ----------------
// CTA 128x256, 512 threads (16 warps, 4M x 4N), warp tile 32x64.
// Software-pipelined fragments: br for next iter preloaded across the barrier.
#define BM 128
#define BN 256
#define BKH 32                  // halves of K per stage
#define NSTAGE 4
#define ROWB 80                 // smem row stride bytes (64 data + 16 pad)
#define A_BYTES (BM * ROWB)     // 10240
#define B_BYTES (BN * ROWB)     // 20480
#define STAGE_BYTES (A_BYTES + B_BYTES)
#define SMEM_GEMM (NSTAGE * STAGE_BYTES)   // 122880

template <bool FIRST>
__global__ void __launch_bounds__(512, 1) gemm_h(
    const __half* __restrict__ A, const __half* __restrict__ Bt,
    const float* __restrict__ bias, __half* __restrict__ C) {
    constexpr int K = FIRST ? IN_DIM : HID_DIM;
    constexpr int N = FIRST ? HID_DIM : OUT_DIM;
    constexpr int NKT = K / BKH;

    extern __shared__ char smem[];
    const uint32_t sb = smem_u32(smem);

    const int tid = threadIdx.x, lane = tid & 31, wid = tid >> 5;
    const int e = blockIdx.z, m0 = blockIdx.x * BM, n0 = blockIdx.y * BN;

    const __half* Ae = A + (FIRST ? (size_t)0 : (size_t)e * NTOK * K) + (size_t)m0 * K;
    const __half* Be = Bt + (size_t)e * (size_t)N * K + (size_t)n0 * K;
    __half* Ce = C + (size_t)e * NTOK * N;

    // loaders (512 threads): A 128x64B = 512 x 16B (1/thread); B 256x64B = 1024 (2/thread)
    const int ar = tid >> 2, ac = tid & 3;
    const __half* aG = Ae + (size_t)ar * K + ac * 8;
    const uint32_t aS = (uint32_t)(ar * ROWB + ac * 16);
    const int brw = tid >> 1, bc = (tid & 1) * 2;
    const __half* bG = Be + (size_t)brw * K + bc * 8;
    const uint32_t bS = (uint32_t)(brw * ROWB + bc * 16);

#define LOADST(c, s) do {                                                   \
        uint32_t _b = sb + (uint32_t)(s) * STAGE_BYTES;                     \
        const __half* _ag = aG + (size_t)(c) * BKH;                         \
        const __half* _bg = bG + (size_t)(c) * BKH;                         \
        cpa16(_b + aS, _ag);                                                \
        uint32_t _bb = _b + A_BYTES + bS;                                   \
        cpa16(_bb, _bg); cpa16(_bb + 16, _bg + 8);                          \
    } while (0)

    // warp tile 32(M) x 64(N): warps 4(M) x 4(N)
    const int wm = (wid >> 2) * 32, wn = (wid & 3) * 64;
    const uint32_t lrow = (uint32_t)(lane & 15);
    const uint32_t lhalf = (uint32_t)((lane >> 4) * 16);
    const uint32_t aLd = (uint32_t)((wm + lrow) * ROWB) + lhalf;
    const uint32_t bLd = A_BYTES + (uint32_t)((wn + lrow) * ROWB) + lhalf;

    float acc[2][8][4];
#pragma unroll
    for (int i = 0; i < 2; i++)
#pragma unroll
        for (int j = 0; j < 8; j++)
#pragma unroll
            for (int r = 0; r < 4; r++) acc[i][j][r] = 0.0f;

    // prologue: 3 stages in flight, then pre-stage br fragments for kt=0
#pragma unroll
    for (int c = 0; c < NSTAGE - 1; c++) {
        LOADST(c, c);
        asm volatile("cp.async.commit_group;" ::: "memory");
    }
    asm volatile("cp.async.wait_group 1;" ::: "memory");  // chunks 0,1 resident
    __syncthreads();

    uint32_t br_cur[4][4], br_nxt[4][4], af[2][4];
#pragma unroll
    for (int t = 0; t < 4; t++) LDM4(br_cur[t], sb + bLd + t * (16 * ROWB));

    for (int kt = 0; kt < NKT; kt++) {
        if (kt + NSTAGE - 1 < NKT) LOADST(kt + NSTAGE - 1, (kt + NSTAGE - 1) & (NSTAGE - 1));
        asm volatile("cp.async.commit_group;" ::: "memory");

        const uint32_t base = sb + (uint32_t)(kt & (NSTAGE - 1)) * STAGE_BYTES;

        // ks = 0: A frags + next-ks B frags issued first, MMAs use preloaded br_cur
#pragma unroll
        for (int i = 0; i < 2; i++) LDM4(af[i], base + aLd + i * (16 * ROWB));
#pragma unroll
        for (int t = 0; t < 4; t++) LDM4(br_nxt[t], base + bLd + t * (16 * ROWB) + 32);
#pragma unroll
        for (int i = 0; i < 2; i++)
#pragma unroll
            for (int j = 0; j < 8; j++) {
                const int t = j >> 1;
                const uint32_t b0 = (j & 1) ? br_cur[t][1] : br_cur[t][0];
                const uint32_t b1 = (j & 1) ? br_cur[t][3] : br_cur[t][2];
                MMA16816(acc[i][j], af[i], b0, b1);
            }

        // ks = 1
#pragma unroll
        for (int i = 0; i < 2; i++) LDM4(af[i], base + aLd + i * (16 * ROWB) + 32);
#pragma unroll
        for (int i = 0; i < 2; i++)
#pragma unroll
            for (int j = 0; j < 8; j++) {
                const int t = j >> 1;
                const uint32_t b0 = (j & 1) ? br_nxt[t][1] : br_nxt[t][0];
                const uint32_t b1 = (j & 1) ? br_nxt[t][3] : br_nxt[t][2];
                MMA16816(acc[i][j], af[i], b0, b1);
            }

        // make chunk kt+1 visible CTA-wide, then preload its br fragments
        if (kt + 1 < NKT) {
            asm volatile("cp.async.wait_group 1;" ::: "memory");
            __syncthreads();
            const uint32_t nb = sb + (uint32_t)((kt + 1) & (NSTAGE - 1)) * STAGE_BYTES;
#pragma unroll
            for (int t = 0; t < 4; t++) LDM4(br_cur[t], nb + bLd + t * (16 * ROWB));
        }
    }

    // epilogue: bias add, fp16 store
    const int g = lane >> 2, tg = lane & 3;
#pragma unroll
    for (int i = 0; i < 2; i++) {
        const int row = m0 + wm + i * 16 + g;
#pragma unroll
        for (int j = 0; j < 8; j++) {
            const int col = n0 + wn + j * 8 + tg * 2;
            const float bv0 = bias[(size_t)e * N + col];
            const float bv1 = bias[(size_t)e * N + col + 1];
            *(__half2*)(Ce + (size_t)row * N + col) =
                __floats2half2_rn(acc[i][j][0] + bv0, acc[i][j][1] + bv1);
            *(__half2*)(Ce + (size_t)(row + 8) * N + col) =
                __floats2half2_rn(acc[i][j][2] + bv0, acc[i][j][3] + bv1);
        }
    }
#undef LOADST
}

// ---------------- weight transpose + fp16 convert: [K,N] -> [N,K] ----------------
template <bool W1SEL>
__global__ void transpose_h(const float* __restrict__ in, int K, int N) {
    __shared__ float t[32][33];
    __half* out = W1SEL ? g_w1t : g_w2t;
    const int e = blockIdx.z;
    const float* ip = in + (size_t)e * K * N;
    __half* op = out + (size_t)e * K * N;
    const int n0 = blockIdx.x * 32, k0 = blockIdx.y * 32;
#pragma unroll
    for (int r = threadIdx.y; r < 32; r += 8)
        t[r][threadIdx.x] = ip[(size_t)(k0 + r) * N + n0 + threadIdx.x];
    __syncthreads();
#pragma unroll
    for (int r = threadIdx.y; r < 32; r += 8)
        op[(size_t)(n0 + r) * K + k0 + threadIdx.x] = __float2half_rn(t[threadIdx.x][r]);
}

// x -> g_xh fp16
__global__ void copy_h(const float* __restrict__ in) {
    const size_t i = ((size_t)blockIdx.x * 256 + threadIdx.x) * 4;
    float4 v = *(const float4*)(in + i);
    __half2* o = (__half2*)(g_xh + i);
    o[0] = __floats2half2_rn(v.x, v.y);
    o[1] = __floats2half2_rn(v.z, v.w);
}

// ---------------- LayerNorm + GELU in place on g_hh (fp16 rows of HID_DIM) ----------------
__global__ void __launch_bounds__(256) ln_gelu_kernel(
    const float* __restrict__ gamma, const float* __restrict__ beta) {
    __shared__ float red[16];
    const size_t row = blockIdx.x;
    const int e = blockIdx.x >> 13;
    __half* p = g_hh + row * (size_t)HID_DIM;
    const float* gm = gamma + (size_t)e * HID_DIM;
    const float* bt = beta + (size_t)e * HID_DIM;
    const int tid = threadIdx.x;

    float vals[16];
    float s = 0.f, s2 = 0.f;
#pragma unroll
    for (int r = 0; r < 4; r++) {
        const int i = tid * 4 + r * 1024;
        __half2 h0 = *(const __half2*)(p + i);
        __half2 h1 = *(const __half2*)(p + i + 2);
        float2 f0 = __half22float2(h0), f1 = __half22float2(h1);
        vals[r * 4 + 0] = f0.x; vals[r * 4 + 1] = f0.y;
        vals[r * 4 + 2] = f1.x; vals[r * 4 + 3] = f1.y;
        s  += f0.x + f0.y + f1.x + f1.y;
        s2 += f0.x * f0.x + f0.y * f0.y + f1.x * f1.x + f1.y * f1.y;
    }
#pragma unroll
    for (int o = 16; o > 0; o >>= 1) {
        s  += __shfl_xor_sync(0xffffffffu, s, o);
        s2 += __shfl_xor_sync(0xffffffffu, s2, o);
    }
    const int wi = tid >> 5, ln = tid & 31;
    if (ln == 0) { red[wi] = s; red[8 + wi] = s2; }
    __syncthreads();
    if (tid == 0) {
        float ts = 0.f, t2 = 0.f;
        for (int k = 0; k < 8; k++) { ts += red[k]; t2 += red[8 + k]; }
        red[0] = ts; red[8] = t2;
    }
    __syncthreads();
    const float invL = 1.0f / (float)HID_DIM;
    const float mean = red[0] * invL;
    const float inv = rsqrtf(red[8] * invL - mean * mean + 1e-5f);
#pragma unroll
    for (int r = 0; r < 4; r++) {
        const int i = tid * 4 + r * 1024;
        float4 gv = *(const float4*)(gm + i);
        float4 bv = *(const float4*)(bt + i);
        float r0 = geluf((vals[r * 4 + 0] - mean) * inv * gv.x + bv.x);
        float r1 = geluf((vals[r * 4 + 1] - mean) * inv * gv.y + bv.y);
        float r2 = geluf((vals[r * 4 + 2] - mean) * inv * gv.z + bv.z);
        float r3 = geluf((vals[r * 4 + 3] - mean) * inv * gv.w + bv.w);
        *(__half2*)(p + i)     = __floats2half2_rn(r0, r1);
        *(__half2*)(p + i + 2) = __floats2half2_rn(r2, r3);
    }
}

// -------- Final: LN(OUT) + GELU per (e,b), weighted sum over e --------
__global__ void __launch_bounds__(256) final_kernel(
    const float* __restrict__ weights, const float* __restrict__ gamma,
    const float* __restrict__ beta, float* __restrict__ out) {
    __shared__ float red[16];
    const int b = blockIdx.x;
    const int tid = threadIdx.x;
    const int wi = tid >> 5, ln = tid & 31;

    float accv[4] = {0.f, 0.f, 0.f, 0.f};
#pragma unroll 1
    for (int e = 0; e < NE; e++) {
        const __half* p = g_yh + ((size_t)e * NTOK + b) * OUT_DIM;
        float vals[4];
        float s = 0.f, s2 = 0.f;
#pragma unroll
        for (int r = 0; r < 4; r++) {
            float v = __half2float(p[tid + r * 256]);
            vals[r] = v;
            s += v; s2 += v * v;
        }
#pragma unroll
        for (int o = 16; o > 0; o >>= 1) {
            s  += __shfl_xor_sync(0xffffffffu, s, o);
            s2 += __shfl_xor_sync(0xffffffffu, s2, o);
        }
        if (ln == 0) { red[wi] = s; red[8 + wi] = s2; }
        __syncthreads();
        if (tid == 0) {
            float ts = 0.f, t2 = 0.f;
            for (int k = 0; k < 8; k++) { ts += red[k]; t2 += red[8 + k]; }
            red[0] = ts; red[8] = t2;
        }
        __syncthreads();
        const float invL = 1.0f / (float)OUT_DIM;
        const float mean = red[0] * invL;
        const float inv = rsqrtf(red[8] * invL - mean * mean + 1e-5f);
        const float w = weights[(size_t)b * NE + e];
#pragma unroll
        for (int r = 0; r < 4; r++) {
            const int i = tid + r * 256;
            const float v = (vals[r] - mean) * inv * gamma[(size_t)e * OUT_DIM + i]
                          + beta[(size_t)e * OUT_DIM + i];
            accv[r] += w * geluf(v);
        }
        __syncthreads();
    }
#pragma unroll
    for (int r = 0; r < 4; r++)
        out[(size_t)b * OUT_DIM + tid + r * 256] = accv[r];
}

// ---------------- launch ----------------
extern "C" void kernel_launch(void* const* d_in, const int* in_sizes, int n_in,
                              void* d_out, int out_size) {
    const float* x   = (const float*)d_in[0];
    const float* wts = (const float*)d_in[1];
    const float* W1  = (const float*)d_in[2];
    const float* b1  = (const float*)d_in[3];
    const float* g1  = (const float*)d_in[4];
    const float* be1 = (const float*)d_in[5];
    const float* W2  = (const float*)d_in[6];
    const float* b2  = (const float*)d_in[7];
    const float* g2  = (const float*)d_in[8];
    const float* be2 = (const float*)d_in[9];
    float* out = (float*)d_out;

    cudaFuncSetAttribute(gemm_h<true>,  cudaFuncAttributeMaxDynamicSharedMemorySize, SMEM_GEMM);
    cudaFuncSetAttribute(gemm_h<false>, cudaFuncAttributeMaxDynamicSharedMemorySize, SMEM_GEMM);

    __half* w1t; cudaGetSymbolAddress((void**)&w1t, g_w1t);
    __half* w2t; cudaGetSymbolAddress((void**)&w2t, g_w2t);
    __half* xh;  cudaGetSymbolAddress((void**)&xh,  g_xh);
    __half* hh;  cudaGetSymbolAddress((void**)&hh,  g_hh);
    __half* yh;  cudaGetSymbolAddress((void**)&yh,  g_yh);

    // prep: transpose+convert weights, convert x
    transpose_h<true ><<<dim3(HID_DIM / 32, IN_DIM / 32, NE), dim3(32, 8)>>>(W1, IN_DIM, HID_DIM);
    transpose_h<false><<<dim3(OUT_DIM / 32, HID_DIM / 32, NE), dim3(32, 8)>>>(W2, HID_DIM, OUT_DIM);
    copy_h<<<(NTOK * IN_DIM) / 1024, 256>>>(x);

    // GEMM1: g_hh = x @ W1 + b1  (fp16)
    gemm_h<true><<<dim3(NTOK / BM, HID_DIM / BN, NE), 512, SMEM_GEMM>>>(xh, w1t, b1, hh);
    // LN + GELU in place on g_hh
    ln_gelu_kernel<<<NE * NTOK, 256>>>(g1, be1);
    // GEMM2: g_yh = hh @ W2 + b2 (fp16)
    gemm_h<false><<<dim3(NTOK / BM, OUT_DIM / BN, NE), 512, SMEM_GEMM>>>(hh, w2t, b2, yh);
    // final LN + GELU + weighted combine
    final_kernel<<<NTOK, 256>>>(wts, g2, be2, out);
}

// round 7
// speedup vs baseline: 1.1190x; 1.1186x over previous
#include <cuda_runtime.h>
#include <cuda_fp16.h>
#include <cstdint>
#include <cstddef>

#define NTOK 8192
#define IN_DIM 1024
#define HID_DIM 4096
#define OUT_DIM 1024
#define NE 8
#define NKT1 (IN_DIM / 32)   // 32 k-chunks for GEMM1
#define NKT2 (HID_DIM / 32)  // 128 k-chunks for GEMM2

// Packed tile buffers (uint4 units; A-tile 128x32h = 8KB = 512 u4, B-tile 256x32h = 16KB = 1024 u4)
__device__ uint4 g_xp[(size_t)64 * NKT1 * 512];            // x packed: (mb, kt) 16MB
__device__ uint4 g_hp[(size_t)NE * 64 * NKT2 * 512];       // h packed: (e*64+mb, kt) 512MB
__device__ uint4 g_w1p[(size_t)NE * 16 * NKT1 * 1024];     // W1^T packed: (e,nb,kt) 64MB
__device__ uint4 g_w2p[(size_t)NE * 4 * NKT2 * 1024];      // W2^T packed 64MB
__device__ __half g_hh[(size_t)NE * NTOK * HID_DIM];       // GEMM1 out, row-major
__device__ __half g_yh[(size_t)NE * NTOK * OUT_DIM];       // GEMM2 out, row-major

// ---------------- helpers ----------------
__device__ __forceinline__ float geluf(float x) {
    return 0.5f * x * (1.0f + erff(x * 0.70710678118654752f));
}
__device__ __forceinline__ uint32_t smem_u32(const void* p) {
    uint32_t a;
    asm("{ .reg .u64 t; cvta.to.shared.u64 t, %1; cvt.u32.u64 %0, t; }" : "=r"(a) : "l"(p));
    return a;
}
__device__ __forceinline__ uint4 pack8h(const float* v) {
    uint4 u;
    __half2 a = __floats2half2_rn(v[0], v[1]);
    __half2 b = __floats2half2_rn(v[2], v[3]);
    __half2 c = __floats2half2_rn(v[4], v[5]);
    __half2 d = __floats2half2_rn(v[6], v[7]);
    u.x = *(uint32_t*)&a; u.y = *(uint32_t*)&b;
    u.z = *(uint32_t*)&c; u.w = *(uint32_t*)&d;
    return u;
}
__device__ __forceinline__ void bulkcp(uint32_t dst, const void* src, uint32_t bytes, uint32_t mbar) {
    asm volatile(
        "cp.async.bulk.shared::cluster.global.mbarrier::complete_tx::bytes [%0], [%1], %2, [%3];"
        :: "r"(dst), "l"(src), "r"(bytes), "r"(mbar) : "memory");
}

#define MBAR_INIT(addr, cnt) \
    asm volatile("mbarrier.init.shared.b64 [%0], %1;" :: "r"(addr), "r"((uint32_t)(cnt)) : "memory")
#define MBAR_EXPECT(addr, n) \
    asm volatile("mbarrier.arrive.expect_tx.shared.b64 _, [%0], %1;" :: "r"(addr), "r"((uint32_t)(n)) : "memory")
#define MBAR_ARRIVE(addr) \
    asm volatile("mbarrier.arrive.shared.b64 _, [%0];" :: "r"(addr) : "memory")
#define MBAR_WAIT(addr, parity) do {                                              \
    uint32_t _m = (addr); uint32_t _p = (parity); uint32_t _d;                    \
    asm volatile("{\n\t.reg .pred p;\n\t"                                         \
        "mbarrier.try_wait.parity.acquire.cta.shared::cta.b64 p, [%1], %2;\n\t"   \
        "selp.b32 %0, 1, 0, p;\n\t}"                                              \
        : "=r"(_d) : "r"(_m), "r"(_p) : "memory");                                \
    if (!_d) {                                                                    \
        asm volatile("{\n\t.reg .pred P1;\n\t"                                    \
            "WAIT_LOOP_%=:\n\t"                                                   \
            "mbarrier.try_wait.parity.acquire.cta.shared::cta.b64 P1, [%0], %1, 0x989680;\n\t" \
            "@P1 bra.uni WAIT_DONE_%=;\n\t"                                       \
            "bra.uni WAIT_LOOP_%=;\n\t"                                           \
            "WAIT_DONE_%=:\n\t}"                                                  \
            :: "r"(_m), "r"(_p) : "memory");                                      \
    }                                                                             \
} while (0)

#define LDM4(r, addr)                                                            \
    asm volatile("ldmatrix.sync.aligned.m8n8.x4.shared.b16 {%0,%1,%2,%3}, [%4];" \
                 : "=r"((r)[0]), "=r"((r)[1]), "=r"((r)[2]), "=r"((r)[3])        \
                 : "r"(addr))

#define MMA16816(c, a, b0, b1)                                                   \
    asm volatile("mma.sync.aligned.m16n8k16.row.col.f32.f16.f16.f32 "            \
                 "{%0,%1,%2,%3}, {%4,%5,%6,%7}, {%8,%9}, {%0,%1,%2,%3};"         \
                 : "+f"((c)[0]), "+f"((c)[1]), "+f"((c)[2]), "+f"((c)[3])        \
                 : "r"((a)[0]), "r"((a)[1]), "r"((a)[2]), "r"((a)[3]),           \
                   "r"(b0), "r"(b1))

// ---------------- bulk-copy GEMM: C[e] = A @ Bt[e]^T + bias[e], fp16 out ----------------
// CTA 128x256, 512 threads (16 warps, 4M x 4N), warp tile 32x64.
// Stages loaded with cp.async.bulk from packed global tiles; mbarrier pipeline, no syncthreads.
#define A_T 8192
#define B_T 16384
#define STG (A_T + B_T)          // 24576
#define SMEM_GEMM (128 + 4 * STG) // 98432

template <bool FIRST>
__global__ void __launch_bounds__(512, 1) gemm_b(
    const uint4* __restrict__ Ap, const uint4* __restrict__ Bp,
    const float* __restrict__ bias, __half* __restrict__ C) {
    constexpr int KDIM = FIRST ? IN_DIM : HID_DIM;
    constexpr int NDIM = FIRST ? HID_DIM : OUT_DIM;
    constexpr int NKT = KDIM / 32;

    extern __shared__ char smem[];
    const uint32_t sb = smem_u32(smem);
    const uint32_t FULLB = sb, EMPTYB = sb + 32, TILES = sb + 128;

    const int tid = threadIdx.x, lane = tid & 31, wid = tid >> 5;
    const int e = blockIdx.z, mb = blockIdx.x, nb = blockIdx.y;

    if (tid == 0) {
#pragma unroll
        for (int s = 0; s < 4; s++) { MBAR_INIT(FULLB + 8 * s, 1); MBAR_INIT(EMPTYB + 8 * s, 16); }
    }
    __syncthreads();

    const uint4* Asrc = Ap + (size_t)(FIRST ? mb : (e * 64 + mb)) * NKT * 512;
    const uint4* Bsrc = Bp + (size_t)(e * (NDIM / 256) + nb) * NKT * 1024;

    auto fill = [&](int c) {
        const int s = c & 3;
        if (c >= 4) MBAR_WAIT(EMPTYB + 8 * s, (uint32_t)(((c >> 2) - 1) & 1));
        MBAR_EXPECT(FULLB + 8 * s, STG);
        bulkcp(TILES + s * STG,       Asrc + (size_t)c * 512,  A_T, FULLB + 8 * s);
        bulkcp(TILES + s * STG + A_T, Bsrc + (size_t)c * 1024, B_T, FULLB + 8 * s);
    };

    if (tid == 0) { fill(0); fill(1); fill(2); }

    // fragment addressing (swizzle: quad ^= (row>>1)&3, rows are 64B)
    const int wm = (wid >> 2) * 32, wn = (wid & 3) * 64;
    uint32_t aOff[2], aXs[2], bOff[4], bXs[4];
#pragma unroll
    for (int i = 0; i < 2; i++) {
        const int r = wm + (lane & 15) + 16 * i;
        aOff[i] = (uint32_t)(r * 64);
        aXs[i] = (uint32_t)(((r >> 1) & 3) << 4);
    }
#pragma unroll
    for (int t = 0; t < 4; t++) {
        const int r = wn + (lane & 15) + 16 * t;
        bOff[t] = (uint32_t)(A_T + r * 64);
        bXs[t] = (uint32_t)(((r >> 1) & 3) << 4);
    }
    const uint32_t qb = (uint32_t)((lane >> 4) << 4);

    float acc[2][8][4];
#pragma unroll
    for (int i = 0; i < 2; i++)
#pragma unroll
        for (int j = 0; j < 8; j++)
#pragma unroll
            for (int r = 0; r < 4; r++) acc[i][j][r] = 0.0f;

    for (int kt = 0; kt < NKT; kt++) {
        if (tid == 0 && kt + 3 < NKT) fill(kt + 3);
        MBAR_WAIT(FULLB + 8 * (kt & 3), (uint32_t)((kt >> 2) & 1));
        const uint32_t st = TILES + (uint32_t)(kt & 3) * STG;
#pragma unroll
        for (int ks = 0; ks < 2; ks++) {
            const uint32_t q = qb + ks * 32;
            uint32_t af[2][4], br[4][4];
#pragma unroll
            for (int i = 0; i < 2; i++) LDM4(af[i], st + aOff[i] + (q ^ aXs[i]));
#pragma unroll
            for (int t = 0; t < 4; t++) LDM4(br[t], st + bOff[t] + (q ^ bXs[t]));
#pragma unroll
            for (int i = 0; i < 2; i++)
#pragma unroll
                for (int j = 0; j < 8; j++) {
                    const int t = j >> 1;
                    const uint32_t b0 = (j & 1) ? br[t][1] : br[t][0];
                    const uint32_t b1 = (j & 1) ? br[t][3] : br[t][2];
                    MMA16816(acc[i][j], af[i], b0, b1);
                }
        }
        __syncwarp();
        if (lane == 0) MBAR_ARRIVE(EMPTYB + 8 * (kt & 3));
    }

    // epilogue: bias add, fp16 store (row-major C)
    __half* Ce = C + (size_t)e * NTOK * NDIM;
    const int m0 = mb * 128, n0 = nb * 256;
    const int g = lane >> 2, tg = lane & 3;
#pragma unroll
    for (int i = 0; i < 2; i++) {
        const int row = m0 + wm + i * 16 + g;
#pragma unroll
        for (int j = 0; j < 8; j++) {
            const int col = n0 + wn + j * 8 + tg * 2;
            const float bv0 = bias[(size_t)e * NDIM + col];
            const float bv1 = bias[(size_t)e * NDIM + col + 1];
            *(__half2*)(Ce + (size_t)row * NDIM + col) =
                __floats2half2_rn(acc[i][j][0] + bv0, acc[i][j][1] + bv1);
            *(__half2*)(Ce + (size_t)(row + 8) * NDIM + col) =
                __floats2half2_rn(acc[i][j][2] + bv0, acc[i][j][3] + bv1);
        }
    }
}

// ---------------- weight pack: W [E][K][N] fp32 -> packed fp16 B-tiles ----------------
template <bool W1SEL>
__global__ void __launch_bounds__(256) pack_w(const float* __restrict__ W, int K, int N) {
    __shared__ __half sm[256][34];
    const int e = blockIdx.z, nb = blockIdx.x, kt = blockIdx.y;
    const int tid = threadIdx.x;
    const float* ip = W + ((size_t)e * K + (size_t)kt * 32) * N + (size_t)nb * 256;
#pragma unroll
    for (int kk = 0; kk < 32; kk++)
        sm[tid][kk] = __float2half_rn(ip[(size_t)kk * N + tid]);
    __syncthreads();
    uint4* op = W1SEL ? g_w1p : g_w2p;
    const size_t tb = ((size_t)(e * (N / 256) + nb) * (K / 32) + kt) * 1024;
    const uint32_t xr = (uint32_t)((tid >> 1) & 3);
#pragma unroll
    for (int q = 0; q < 4; q++) {
        uint4 u;
        const __half2* s2 = (const __half2*)&sm[tid][q * 8];
        u.x = *(const uint32_t*)&s2[0]; u.y = *(const uint32_t*)&s2[1];
        u.z = *(const uint32_t*)&s2[2]; u.w = *(const uint32_t*)&s2[3];
        op[tb + (size_t)tid * 4 + ((uint32_t)q ^ xr)] = u;
    }
}

// ---------------- x pack: fp32 [8192,1024] -> packed fp16 A-tiles ----------------
__global__ void __launch_bounds__(256) pack_x(const float* __restrict__ x) {
    const int mb = blockIdx.x, kt = blockIdx.y, tid = threadIdx.x;
    const int r = tid >> 1, h16 = tid & 1;
    const float* ip = x + (size_t)(mb * 128 + r) * 1024 + kt * 32 + h16 * 16;
    float v[16];
    *(float4*)(v)      = *(const float4*)(ip);
    *(float4*)(v + 4)  = *(const float4*)(ip + 4);
    *(float4*)(v + 8)  = *(const float4*)(ip + 8);
    *(float4*)(v + 12) = *(const float4*)(ip + 12);
    const size_t tb = ((size_t)mb * NKT1 + kt) * 512;
    const uint32_t xr = (uint32_t)((r >> 1) & 3);
    const uint32_t q0 = (uint32_t)(h16 * 2);
    g_xp[tb + (size_t)r * 4 + (q0 ^ xr)]       = pack8h(v);
    g_xp[tb + (size_t)r * 4 + ((q0 + 1) ^ xr)] = pack8h(v + 8);
}

// ------- LayerNorm + GELU: g_hh row-major -> g_hp packed A-tiles (fused pack) -------
__global__ void __launch_bounds__(256) ln_gelu_kernel(
    const float* __restrict__ gamma, const float* __restrict__ beta) {
    __shared__ float red[16];
    const int bid = blockIdx.x;
    const int e = bid >> 13, m = bid & 8191;
    const __half* p = g_hh + (size_t)bid * HID_DIM;
    const float* gm = gamma + (size_t)e * HID_DIM;
    const float* bt = beta + (size_t)e * HID_DIM;
    const int tid = threadIdx.x;

    float vals[16];
    float s = 0.f, s2 = 0.f;
    const __half2* ph = (const __half2*)(p + tid * 16);
#pragma unroll
    for (int i = 0; i < 8; i++) {
        float2 f = __half22float2(ph[i]);
        vals[2 * i] = f.x; vals[2 * i + 1] = f.y;
        s += f.x + f.y;
        s2 += f.x * f.x + f.y * f.y;
    }
#pragma unroll
    for (int o = 16; o > 0; o >>= 1) {
        s  += __shfl_xor_sync(0xffffffffu, s, o);
        s2 += __shfl_xor_sync(0xffffffffu, s2, o);
    }
    const int wi = tid >> 5, ln = tid & 31;
    if (ln == 0) { red[wi] = s; red[8 + wi] = s2; }
    __syncthreads();
    if (tid == 0) {
        float ts = 0.f, t2 = 0.f;
        for (int k = 0; k < 8; k++) { ts += red[k]; t2 += red[8 + k]; }
        red[0] = ts; red[8] = t2;
    }
    __syncthreads();
    const float invL = 1.0f / (float)HID_DIM;
    const float mean = red[0] * invL;
    const float inv = rsqrtf(red[8] * invL - mean * mean + 1e-5f);
    const float* gmp = gm + tid * 16;
    const float* btp = bt + tid * 16;
#pragma unroll
    for (int i = 0; i < 16; i++)
        vals[i] = geluf((vals[i] - mean) * inv * gmp[i] + btp[i]);

    const int mb = m >> 7, r = m & 127, kt = tid >> 1;
    const uint32_t q0 = (uint32_t)((tid & 1) * 2);
    const uint32_t xr = (uint32_t)((r >> 1) & 3);
    const size_t tb = ((size_t)(e * 64 + mb) * NKT2 + kt) * 512;
    g_hp[tb + (size_t)r * 4 + (q0 ^ xr)]       = pack8h(vals);
    g_hp[tb + (size_t)r * 4 + ((q0 + 1) ^ xr)] = pack8h(vals + 8);
}

// -------- Final: LN(OUT) + GELU per (e,b), weighted sum over e --------
__global__ void __launch_bounds__(256) final_kernel(
    const float* __restrict__ weights, const float* __restrict__ gamma,
    const float* __restrict__ beta, float* __restrict__ out) {
    __shared__ float red[16];
    const int b = blockIdx.x;
    const int tid = threadIdx.x;
    const int wi = tid >> 5, ln = tid & 31;

    float accv[4] = {0.f, 0.f, 0.f, 0.f};
#pragma unroll 1
    for (int e = 0; e < NE; e++) {
        const __half* p = g_yh + ((size_t)e * NTOK + b) * OUT_DIM;
        float vals[4];
        float s = 0.f, s2 = 0.f;
#pragma unroll
        for (int r = 0; r < 4; r++) {
            float v = __half2float(p[tid + r * 256]);
            vals[r] = v;
            s += v; s2 += v * v;
        }
#pragma unroll
        for (int o = 16; o > 0; o >>= 1) {
            s  += __shfl_xor_sync(0xffffffffu, s, o);
            s2 += __shfl_xor_sync(0xffffffffu, s2, o);
        }
        if (ln == 0) { red[wi] = s; red[8 + wi] = s2; }
        __syncthreads();
        if (tid == 0) {
            float ts = 0.f, t2 = 0.f;
            for (int k = 0; k < 8; k++) { ts += red[k]; t2 += red[8 + k]; }
            red[0] = ts; red[8] = t2;
        }
        __syncthreads();
        const float invL = 1.0f / (float)OUT_DIM;
        const float mean = red[0] * invL;
        const float inv = rsqrtf(red[8] * invL - mean * mean + 1e-5f);
        const float w = weights[(size_t)b * NE + e];
#pragma unroll
        for (int r = 0; r < 4; r++) {
            const int i = tid + r * 256;
            const float v = (vals[r] - mean) * inv * gamma[(size_t)e * OUT_DIM + i]
                          + beta[(size_t)e * OUT_DIM + i];
            accv[r] += w * geluf(v);
        }
        __syncthreads();
    }
#pragma unroll
    for (int r = 0; r < 4; r++)
        out[(size_t)b * OUT_DIM + tid + r * 256] = accv[r];
}

// ---------------- launch ----------------
extern "C" void kernel_launch(void* const* d_in, const int* in_sizes, int n_in,
                              void* d_out, int out_size) {
    const float* x   = (const float*)d_in[0];
    const float* wts = (const float*)d_in[1];
    const float* W1  = (const float*)d_in[2];
    const float* b1  = (const float*)d_in[3];
    const float* g1  = (const float*)d_in[4];
    const float* be1 = (const float*)d_in[5];
    const float* W2  = (const float*)d_in[6];
    const float* b2  = (const float*)d_in[7];
    const float* g2  = (const float*)d_in[8];
    const float* be2 = (const float*)d_in[9];
    float* out = (float*)d_out;

    cudaFuncSetAttribute(gemm_b<true>,  cudaFuncAttributeMaxDynamicSharedMemorySize, SMEM_GEMM);
    cudaFuncSetAttribute(gemm_b<false>, cudaFuncAttributeMaxDynamicSharedMemorySize, SMEM_GEMM);

    uint4* xp;  cudaGetSymbolAddress((void**)&xp,  g_xp);
    uint4* hp;  cudaGetSymbolAddress((void**)&hp,  g_hp);
    uint4* w1p; cudaGetSymbolAddress((void**)&w1p, g_w1p);
    uint4* w2p; cudaGetSymbolAddress((void**)&w2p, g_w2p);
    __half* hh; cudaGetSymbolAddress((void**)&hh,  g_hh);
    __half* yh; cudaGetSymbolAddress((void**)&yh,  g_yh);

    // prep: pack weights and x into bulk-copy tile layout
    pack_w<true ><<<dim3(HID_DIM / 256, NKT1, NE), 256>>>(W1, IN_DIM, HID_DIM);
    pack_w<false><<<dim3(OUT_DIM / 256, NKT2, NE), 256>>>(W2, HID_DIM, OUT_DIM);
    pack_x<<<dim3(64, NKT1), 256>>>(x);

    // GEMM1: g_hh = x @ W1 + b1
    gemm_b<true><<<dim3(64, HID_DIM / 256, NE), 512, SMEM_GEMM>>>(xp, w1p, b1, hh);
    // LN + GELU, writes packed g_hp
    ln_gelu_kernel<<<NE * NTOK, 256>>>(g1, be1);
    // GEMM2: g_yh = h @ W2 + b2
    gemm_b<false><<<dim3(64, OUT_DIM / 256, NE), 512, SMEM_GEMM>>>(hp, w2p, b2, yh);
    // final LN + GELU + weighted combine
    final_kernel<<<NTOK, 256>>>(wts, g2, be2, out);
}